// round 12
// baseline (speedup 1.0000x reference)
#include <cuda_runtime.h>
#include <cuda_bf16.h>

// Problem dims
#define BB 64
#define TT 4096
#define DD 67
#define HH 128
#define NTOK (BB * TT)   // 262144

typedef unsigned long long ull;

// Device scratch (allocation-free per harness rules)
__device__ float g_feat[(long long)NTOK * HH];    // 134 MB
__device__ float g_pre [(long long)NTOK * 512];   // 537 MB
__device__ float g_seq [(long long)NTOK * HH];    // 134 MB

// ---------------- f32x2 helpers ----------------
__device__ __forceinline__ void fma2(ull &acc, ull a, ull b) {
    asm("fma.rn.f32x2 %0, %1, %2, %0;" : "+l"(acc) : "l"(a), "l"(b));
}
__device__ __forceinline__ ull pack2(float lo, float hi) {
    ull u; asm("mov.b64 %0, {%1, %2};" : "=l"(u) : "f"(lo), "f"(hi)); return u;
}
__device__ __forceinline__ ull dup2(float a) {
    ull u; asm("mov.b64 %0, {%1, %1};" : "=l"(u) : "f"(a)); return u;
}
__device__ __forceinline__ float2 unpack2(ull u) {
    float2 r; asm("mov.b64 {%0, %1}, %2;" : "=f"(r.x), "=f"(r.y) : "l"(u)); return r;
}
__device__ __forceinline__ float sum2(ull u) {
    float2 r = unpack2(u); return r.x + r.y;
}

// =====================================================================
// K1: feat = silu(LN2(LN1(x) @ proj_w + proj_b))
//     128 threads, 8 tokens per block
// =====================================================================
__global__ void __launch_bounds__(128) k1_feat(
    const float* __restrict__ x,
    const float* __restrict__ g1, const float* __restrict__ b1,
    const float* __restrict__ pw, const float* __restrict__ pb,
    const float* __restrict__ g2, const float* __restrict__ b2)
{
    __shared__ __align__(16) float pwt[HH * 72];   // transposed weights [h][d]
    __shared__ __align__(16) float xs[8][72];
    __shared__ float ys[8][HH];
    __shared__ float mu[8], rs[8];

    const int tid = threadIdx.x;
    const long long n0 = (long long)blockIdx.x * 8;

    // load + transpose proj weights: pwt[h][d] = pw[d*128 + h]
    for (int i = tid; i < DD * HH; i += 128) {
        int d = i >> 7, h = i & 127;
        pwt[h * 72 + d] = pw[i];
    }
    // load x tile
    for (int i = tid; i < 8 * DD; i += 128) {
        int tk = i / DD, d = i % DD;
        xs[tk][d] = x[(n0 + tk) * DD + d];
    }
    __syncthreads();

    const int wid = tid >> 5, lane = tid & 31;
    // LN1 stats: warp w handles tokens 2w, 2w+1
    for (int tk = wid * 2; tk < wid * 2 + 2; tk++) {
        float s = 0.f, sq = 0.f;
        for (int d = lane; d < DD; d += 32) { float v = xs[tk][d]; s += v; sq += v * v; }
        #pragma unroll
        for (int o = 16; o; o >>= 1) {
            s  += __shfl_xor_sync(0xffffffffu, s,  o);
            sq += __shfl_xor_sync(0xffffffffu, sq, o);
        }
        if (lane == 0) {
            float m = s / (float)DD;
            mu[tk] = m;
            rs[tk] = rsqrtf(sq / (float)DD - m * m + 1e-5f);
        }
    }
    __syncthreads();
    for (int i = tid; i < 8 * DD; i += 128) {
        int tk = i / DD, d = i % DD;
        xs[tk][d] = (xs[tk][d] - mu[tk]) * rs[tk] * g1[d] + b1[d];
    }
    __syncthreads();

    // projection: thread h computes ys[tk][h] for all 8 tokens
    {
        const int h = tid;
        const float* wrow = pwt + h * 72;
        float acc[8];
        #pragma unroll
        for (int r = 0; r < 8; r++) acc[r] = pb[h];
        #pragma unroll
        for (int d4 = 0; d4 < 16; d4++) {
            float4 wv = *(const float4*)&wrow[d4 * 4];
            #pragma unroll
            for (int r = 0; r < 8; r++) {
                float4 xv = *(const float4*)&xs[r][d4 * 4];
                acc[r] += xv.x * wv.x + xv.y * wv.y + xv.z * wv.z + xv.w * wv.w;
            }
        }
        #pragma unroll
        for (int r = 0; r < 8; r++) {
            acc[r] += xs[r][64] * wrow[64] + xs[r][65] * wrow[65] + xs[r][66] * wrow[66];
            ys[r][h] = acc[r];
        }
    }
    __syncthreads();

    // LN2 stats over H=128
    for (int tk = wid * 2; tk < wid * 2 + 2; tk++) {
        float s = 0.f, sq = 0.f;
        #pragma unroll
        for (int hh = lane; hh < HH; hh += 32) { float v = ys[tk][hh]; s += v; sq += v * v; }
        #pragma unroll
        for (int o = 16; o; o >>= 1) {
            s  += __shfl_xor_sync(0xffffffffu, s,  o);
            sq += __shfl_xor_sync(0xffffffffu, sq, o);
        }
        if (lane == 0) {
            float m = s / (float)HH;
            mu[tk] = m;
            rs[tk] = rsqrtf(sq / (float)HH - m * m + 1e-5f);
        }
    }
    __syncthreads();
    {
        const int h = tid;
        const float gv = g2[h], bv = b2[h];
        #pragma unroll
        for (int r = 0; r < 8; r++) {
            float v = (ys[r][h] - mu[r]) * rs[r] * gv + bv;
            g_feat[(n0 + r) * HH + h] = v / (1.f + expf(-v));
        }
    }
}

// =====================================================================
// K2: pre[tok, g*128+n] = feat[tok,:] @ Wx_g + bias_g  (x-part rows 0..127)
//     tiles 128(M)x128(N), K=128; 256 threads, 8x8 micro-tiles, f32x2
// =====================================================================
#define K2_SMEM_BYTES ((128 * 129 + 128 * 132) * 4)

__global__ void __launch_bounds__(256) k2_pre(
    const float* __restrict__ w0, const float* __restrict__ w1,
    const float* __restrict__ w2, const float* __restrict__ w3,
    const float* __restrict__ bb0, const float* __restrict__ bb1,
    const float* __restrict__ bb2, const float* __restrict__ bb3)
{
    extern __shared__ float sm2[];
    float* As = sm2;                 // [128][129]
    float* Bs = sm2 + 128 * 129;     // [128][132]  (132*4 = 528 bytes, 16B multiple)

    const int g = blockIdx.y;
    const float* W  = (g == 0) ? w0  : (g == 1) ? w1  : (g == 2) ? w2  : w3;
    const float* Bv = (g == 0) ? bb0 : (g == 1) ? bb1 : (g == 2) ? bb2 : bb3;

    const int tid = threadIdx.x;
    const long long m0 = (long long)blockIdx.x * 128;

    for (int i = tid; i < 128 * 128; i += 256) {
        int m = i >> 7, k = i & 127;
        As[m * 129 + k] = g_feat[(m0 + m) * 128 + k];
    }
    for (int i = tid; i < 128 * 128; i += 256) {
        int k = i >> 7, n = i & 127;
        Bs[k * 132 + n] = W[k * 128 + n];   // x-part rows 0..127
    }
    __syncthreads();

    const int tx = tid & 15, ty = tid >> 4;
    ull acc[8][4];
    #pragma unroll
    for (int j = 0; j < 4; j++) {
        ull bb = pack2(Bv[tx * 8 + j * 2], Bv[tx * 8 + j * 2 + 1]);
        #pragma unroll
        for (int i = 0; i < 8; i++) acc[i][j] = bb;
    }

    const float* ap = &As[(ty * 8) * 129];
    for (int k = 0; k < 128; k++) {
        const ulonglong2* br = reinterpret_cast<const ulonglong2*>(Bs + k * 132 + tx * 8);
        ulonglong2 bA = br[0], bB = br[1];
        #pragma unroll
        for (int i = 0; i < 8; i++) {
            ull ad = dup2(ap[i * 129 + k]);
            fma2(acc[i][0], bA.x, ad);
            fma2(acc[i][1], bA.y, ad);
            fma2(acc[i][2], bB.x, ad);
            fma2(acc[i][3], bB.y, ad);
        }
    }

    #pragma unroll
    for (int i = 0; i < 8; i++) {
        long long row = m0 + ty * 8 + i;
        float* dst = g_pre + row * 512 + g * 128 + tx * 8;
        float2 p0 = unpack2(acc[i][0]), p1 = unpack2(acc[i][1]);
        float2 p2 = unpack2(acc[i][2]), p3 = unpack2(acc[i][3]);
        *(float4*)(dst)     = make_float4(p0.x, p0.y, p1.x, p1.y);
        *(float4*)(dst + 4) = make_float4(p2.x, p2.y, p3.x, p3.y);
    }
}

// =====================================================================
// K3: CfC recurrence. One CTA per batch, 256 threads, 2 columns/thread.
//     h-part weights: 48 k-pairs/col in registers + 16 k-pairs/col in smem.
// =====================================================================
#define NREG 48
#define NSM  (64 - NREG)   // 16 smem pairs per column
#define K3_SMEM_BYTES (512 + 2048 + NSM * 512 * 8)   // hs2 + v + ws = 68096

__global__ void __launch_bounds__(256, 1) k3_rec(
    const float* __restrict__ w0, const float* __restrict__ w1,
    const float* __restrict__ w2, const float* __restrict__ w3,
    const float* __restrict__ dt)
{
    extern __shared__ unsigned char sm3[];
    ull*   hs2 = (ull*)sm3;                          // 64 packed h pairs (512 B)
    float* vsh = (float*)(sm3 + 512);                // 512 floats (2 KB)
    ull*   ws  = (ull*)(sm3 + 512 + 2048);           // [NSM][512] weight pairs

    const int tid = threadIdx.x;
    const int b = blockIdx.x;
    const int c0 = tid, c1 = tid + 256;

    const float* gsel[4] = { w0, w1, w2, w3 };
    const int j0 = c0 & 127, j1 = c1 & 127;
    // base of h-part rows (row 128) at our column
    const float* p0 = gsel[c0 >> 7] + 128 * 128 + j0;
    const float* p1 = gsel[c1 >> 7] + 128 * 128 + j1;

    ull wr0[NREG], wr1[NREG];
    #pragma unroll
    for (int p = 0; p < NREG; p++) {
        wr0[p] = pack2(p0[(2 * p) * 128], p0[(2 * p + 1) * 128]);
        wr1[p] = pack2(p1[(2 * p) * 128], p1[(2 * p + 1) * 128]);
    }
    #pragma unroll
    for (int p = NREG; p < 64; p++) {
        ws[(p - NREG) * 512 + c0] = pack2(p0[(2 * p) * 128], p0[(2 * p + 1) * 128]);
        ws[(p - NREG) * 512 + c1] = pack2(p1[(2 * p) * 128], p1[(2 * p + 1) * 128]);
    }
    if (tid < 64) hs2[tid] = 0ull;   // h0 = 0
    __syncthreads();

    const float* preb = g_pre + (long long)b * TT * 512;
    const float* dtb  = dt    + (long long)b * TT;
    float*       seqb = g_seq + (long long)b * TT * 128;

    for (int t = 0; t < TT; t++) {
        // prefetch this step's pre values + dt (consumed after the MAC loop)
        const float pre0 = __ldg(preb + (long long)t * 512 + c0);
        const float pre1 = __ldg(preb + (long long)t * 512 + c1);
        const float dtt  = __ldg(dtb + t) * 10.0f;

        ull a0 = 0ull, a1 = 0ull;
        #pragma unroll
        for (int p = 0; p < NREG; p++) {
            ull hp = hs2[p];
            fma2(a0, wr0[p], hp);
            fma2(a1, wr1[p], hp);
        }
        #pragma unroll
        for (int p = NREG; p < 64; p++) {
            ull hp = hs2[p];
            fma2(a0, ws[(p - NREG) * 512 + c0], hp);
            fma2(a1, ws[(p - NREG) * 512 + c1], hp);
        }
        vsh[c0] = sum2(a0) + pre0;
        vsh[c1] = sum2(a1) + pre1;
        __syncthreads();   // all h reads done; v complete

        if (tid < 128) {
            const int j = tid;
            float ff1 = tanhf(vsh[j]);
            float ff2 = tanhf(vsh[128 + j]);
            float z   = vsh[256 + j] * dtt + vsh[384 + j];
            float gate = 1.0f / (1.0f + expf(-z));
            float hn = ff1 + gate * (ff2 - ff1);
            seqb[(long long)t * 128 + j] = hn;
            ((float*)hs2)[j] = hn;
        }
        __syncthreads();   // h ready for next step
    }
}

// =====================================================================
// K4: logits[tok] = seq[tok,:] . head_w + head_b   (one warp per token)
// =====================================================================
__global__ void __launch_bounds__(256) k4_head(
    const float* __restrict__ hw, const float* __restrict__ hb,
    float* __restrict__ out)
{
    const int tid = threadIdx.x;
    const int lane = tid & 31, w = tid >> 5;
    const long long tok = (long long)blockIdx.x * 8 + w;
    float4 s  = *(const float4*)(g_seq + tok * 128 + lane * 4);
    float4 hv = *(const float4*)(hw + lane * 4);
    float p = s.x * hv.x + s.y * hv.y + s.z * hv.z + s.w * hv.w;
    #pragma unroll
    for (int o = 16; o; o >>= 1) p += __shfl_xor_sync(0xffffffffu, p, o);
    if (lane == 0) out[tok] = p + hb[0];
}

// =====================================================================
extern "C" void kernel_launch(void* const* d_in, const int* in_sizes, int n_in,
                              void* d_out, int out_size)
{
    const float* x      = (const float*)d_in[0];
    const float* dt     = (const float*)d_in[1];
    const float* ln_in_g= (const float*)d_in[2];
    const float* ln_in_b= (const float*)d_in[3];
    const float* proj_w = (const float*)d_in[4];
    const float* proj_b = (const float*)d_in[5];
    const float* ln_p_g = (const float*)d_in[6];
    const float* ln_p_b = (const float*)d_in[7];
    const float* ff1_w  = (const float*)d_in[8];
    const float* ff1_b  = (const float*)d_in[9];
    const float* ff2_w  = (const float*)d_in[10];
    const float* ff2_b  = (const float*)d_in[11];
    const float* ta_w   = (const float*)d_in[12];
    const float* ta_b   = (const float*)d_in[13];
    const float* tb_w   = (const float*)d_in[14];
    const float* tb_b   = (const float*)d_in[15];
    const float* head_w = (const float*)d_in[16];
    const float* head_b = (const float*)d_in[17];
    float* out = (float*)d_out;

    cudaFuncSetAttribute(k2_pre, cudaFuncAttributeMaxDynamicSharedMemorySize, K2_SMEM_BYTES);
    cudaFuncSetAttribute(k3_rec, cudaFuncAttributeMaxDynamicSharedMemorySize, K3_SMEM_BYTES);

    k1_feat<<<NTOK / 8, 128>>>(x, ln_in_g, ln_in_b, proj_w, proj_b, ln_p_g, ln_p_b);

    dim3 g2(NTOK / 128, 4);
    k2_pre<<<g2, 256, K2_SMEM_BYTES>>>(ff1_w, ff2_w, ta_w, tb_w,
                                       ff1_b, ff2_b, ta_b, tb_b);

    k3_rec<<<BB, 256, K3_SMEM_BYTES>>>(ff1_w, ff2_w, ta_w, tb_w, dt);

    k4_head<<<NTOK / 8, 256>>>(head_w, head_b, out);
}

// round 13
// speedup vs baseline: 1.0004x; 1.0004x over previous
#include <cuda_runtime.h>
#include <cuda_bf16.h>

// Problem dims
#define BB 64
#define TT 4096
#define DD 67
#define HH 128
#define NTOK (BB * TT)   // 262144

typedef unsigned long long ull;

// Device scratch (allocation-free per harness rules)
__device__ float g_feat[(long long)NTOK * HH];    // 134 MB
__device__ float g_pre [(long long)NTOK * 512];   // 537 MB
__device__ float g_seq [(long long)NTOK * HH];    // 134 MB

// ---------------- f32x2 helpers ----------------
__device__ __forceinline__ void fma2(ull &acc, ull a, ull b) {
    asm("fma.rn.f32x2 %0, %1, %2, %0;" : "+l"(acc) : "l"(a), "l"(b));
}
__device__ __forceinline__ ull pack2(float lo, float hi) {
    ull u; asm("mov.b64 %0, {%1, %2};" : "=l"(u) : "f"(lo), "f"(hi)); return u;
}
__device__ __forceinline__ ull dup2(float a) {
    ull u; asm("mov.b64 %0, {%1, %1};" : "=l"(u) : "f"(a)); return u;
}
__device__ __forceinline__ float2 unpack2(ull u) {
    float2 r; asm("mov.b64 {%0, %1}, %2;" : "=f"(r.x), "=f"(r.y) : "l"(u)); return r;
}
__device__ __forceinline__ float sum2(ull u) {
    float2 r = unpack2(u); return r.x + r.y;
}

// =====================================================================
// K1: feat = silu(LN2(LN1(x) @ proj_w + proj_b))
//     128 threads, 8 tokens per block
// =====================================================================
__global__ void __launch_bounds__(128) k1_feat(
    const float* __restrict__ x,
    const float* __restrict__ g1, const float* __restrict__ b1,
    const float* __restrict__ pw, const float* __restrict__ pb,
    const float* __restrict__ g2, const float* __restrict__ b2)
{
    __shared__ __align__(16) float pwt[HH * 72];   // transposed weights [h][d]
    __shared__ __align__(16) float xs[8][72];
    __shared__ float ys[8][HH];
    __shared__ float mu[8], rs[8];

    const int tid = threadIdx.x;
    const long long n0 = (long long)blockIdx.x * 8;

    // load + transpose proj weights: pwt[h][d] = pw[d*128 + h]
    for (int i = tid; i < DD * HH; i += 128) {
        int d = i >> 7, h = i & 127;
        pwt[h * 72 + d] = pw[i];
    }
    // load x tile
    for (int i = tid; i < 8 * DD; i += 128) {
        int tk = i / DD, d = i % DD;
        xs[tk][d] = x[(n0 + tk) * DD + d];
    }
    __syncthreads();

    const int wid = tid >> 5, lane = tid & 31;
    // LN1 stats: warp w handles tokens 2w, 2w+1
    for (int tk = wid * 2; tk < wid * 2 + 2; tk++) {
        float s = 0.f, sq = 0.f;
        for (int d = lane; d < DD; d += 32) { float v = xs[tk][d]; s += v; sq += v * v; }
        #pragma unroll
        for (int o = 16; o; o >>= 1) {
            s  += __shfl_xor_sync(0xffffffffu, s,  o);
            sq += __shfl_xor_sync(0xffffffffu, sq, o);
        }
        if (lane == 0) {
            float m = s / (float)DD;
            mu[tk] = m;
            rs[tk] = rsqrtf(sq / (float)DD - m * m + 1e-5f);
        }
    }
    __syncthreads();
    for (int i = tid; i < 8 * DD; i += 128) {
        int tk = i / DD, d = i % DD;
        xs[tk][d] = (xs[tk][d] - mu[tk]) * rs[tk] * g1[d] + b1[d];
    }
    __syncthreads();

    // projection: thread h computes ys[tk][h] for all 8 tokens
    {
        const int h = tid;
        const float* wrow = pwt + h * 72;
        float acc[8];
        #pragma unroll
        for (int r = 0; r < 8; r++) acc[r] = pb[h];
        #pragma unroll
        for (int d4 = 0; d4 < 16; d4++) {
            float4 wv = *(const float4*)&wrow[d4 * 4];
            #pragma unroll
            for (int r = 0; r < 8; r++) {
                float4 xv = *(const float4*)&xs[r][d4 * 4];
                acc[r] += xv.x * wv.x + xv.y * wv.y + xv.z * wv.z + xv.w * wv.w;
            }
        }
        #pragma unroll
        for (int r = 0; r < 8; r++) {
            acc[r] += xs[r][64] * wrow[64] + xs[r][65] * wrow[65] + xs[r][66] * wrow[66];
            ys[r][h] = acc[r];
        }
    }
    __syncthreads();

    // LN2 stats over H=128
    for (int tk = wid * 2; tk < wid * 2 + 2; tk++) {
        float s = 0.f, sq = 0.f;
        #pragma unroll
        for (int hh = lane; hh < HH; hh += 32) { float v = ys[tk][hh]; s += v; sq += v * v; }
        #pragma unroll
        for (int o = 16; o; o >>= 1) {
            s  += __shfl_xor_sync(0xffffffffu, s,  o);
            sq += __shfl_xor_sync(0xffffffffu, sq, o);
        }
        if (lane == 0) {
            float m = s / (float)HH;
            mu[tk] = m;
            rs[tk] = rsqrtf(sq / (float)HH - m * m + 1e-5f);
        }
    }
    __syncthreads();
    {
        const int h = tid;
        const float gv = g2[h], bv = b2[h];
        #pragma unroll
        for (int r = 0; r < 8; r++) {
            float v = (ys[r][h] - mu[r]) * rs[r] * gv + bv;
            g_feat[(n0 + r) * HH + h] = v / (1.f + expf(-v));
        }
    }
}

// =====================================================================
// K2: pre[tok, g*128+n] = feat[tok,:] @ Wx_g + bias_g  (x-part rows 0..127)
//     tiles 128(M)x128(N), K=128; 256 threads, 8x8 micro-tiles, f32x2
// =====================================================================
#define K2_SMEM_BYTES ((128 * 129 + 128 * 132) * 4)

__global__ void __launch_bounds__(256) k2_pre(
    const float* __restrict__ w0, const float* __restrict__ w1,
    const float* __restrict__ w2, const float* __restrict__ w3,
    const float* __restrict__ bb0, const float* __restrict__ bb1,
    const float* __restrict__ bb2, const float* __restrict__ bb3)
{
    extern __shared__ float sm2[];
    float* As = sm2;                 // [128][129]
    float* Bs = sm2 + 128 * 129;     // [128][132]  (132*4 = 528 bytes, 16B multiple)

    const int g = blockIdx.y;
    const float* W  = (g == 0) ? w0  : (g == 1) ? w1  : (g == 2) ? w2  : w3;
    const float* Bv = (g == 0) ? bb0 : (g == 1) ? bb1 : (g == 2) ? bb2 : bb3;

    const int tid = threadIdx.x;
    const long long m0 = (long long)blockIdx.x * 128;

    for (int i = tid; i < 128 * 128; i += 256) {
        int m = i >> 7, k = i & 127;
        As[m * 129 + k] = g_feat[(m0 + m) * 128 + k];
    }
    for (int i = tid; i < 128 * 128; i += 256) {
        int k = i >> 7, n = i & 127;
        Bs[k * 132 + n] = W[k * 128 + n];   // x-part rows 0..127
    }
    __syncthreads();

    const int tx = tid & 15, ty = tid >> 4;
    ull acc[8][4];
    #pragma unroll
    for (int j = 0; j < 4; j++) {
        ull bb = pack2(Bv[tx * 8 + j * 2], Bv[tx * 8 + j * 2 + 1]);
        #pragma unroll
        for (int i = 0; i < 8; i++) acc[i][j] = bb;
    }

    const float* ap = &As[(ty * 8) * 129];
    for (int k = 0; k < 128; k++) {
        const ulonglong2* br = reinterpret_cast<const ulonglong2*>(Bs + k * 132 + tx * 8);
        ulonglong2 bA = br[0], bB = br[1];
        #pragma unroll
        for (int i = 0; i < 8; i++) {
            ull ad = dup2(ap[i * 129 + k]);
            fma2(acc[i][0], bA.x, ad);
            fma2(acc[i][1], bA.y, ad);
            fma2(acc[i][2], bB.x, ad);
            fma2(acc[i][3], bB.y, ad);
        }
    }

    #pragma unroll
    for (int i = 0; i < 8; i++) {
        long long row = m0 + ty * 8 + i;
        float* dst = g_pre + row * 512 + g * 128 + tx * 8;
        float2 p0 = unpack2(acc[i][0]), p1 = unpack2(acc[i][1]);
        float2 p2 = unpack2(acc[i][2]), p3 = unpack2(acc[i][3]);
        *(float4*)(dst)     = make_float4(p0.x, p0.y, p1.x, p1.y);
        *(float4*)(dst + 4) = make_float4(p2.x, p2.y, p3.x, p3.y);
    }
}

// =====================================================================
// K3: CfC recurrence. One CTA per batch, 256 threads, 2 columns/thread.
//     h-part weights: 48 k-pairs/col in registers + 16 k-pairs/col in smem.
// =====================================================================
#define NREG 48
#define NSM  (64 - NREG)   // 16 smem pairs per column
#define K3_SMEM_BYTES (512 + 2048 + NSM * 512 * 8)   // hs2 + v + ws = 68096

__global__ void __launch_bounds__(256, 1) k3_rec(
    const float* __restrict__ w0, const float* __restrict__ w1,
    const float* __restrict__ w2, const float* __restrict__ w3,
    const float* __restrict__ dt)
{
    extern __shared__ unsigned char sm3[];
    ull*   hs2 = (ull*)sm3;                          // 64 packed h pairs (512 B)
    float* vsh = (float*)(sm3 + 512);                // 512 floats (2 KB)
    ull*   ws  = (ull*)(sm3 + 512 + 2048);           // [NSM][512] weight pairs

    const int tid = threadIdx.x;
    const int b = blockIdx.x;
    const int c0 = tid, c1 = tid + 256;

    const float* gsel[4] = { w0, w1, w2, w3 };
    const int j0 = c0 & 127, j1 = c1 & 127;
    // base of h-part rows (row 128) at our column
    const float* p0 = gsel[c0 >> 7] + 128 * 128 + j0;
    const float* p1 = gsel[c1 >> 7] + 128 * 128 + j1;

    ull wr0[NREG], wr1[NREG];
    #pragma unroll
    for (int p = 0; p < NREG; p++) {
        wr0[p] = pack2(p0[(2 * p) * 128], p0[(2 * p + 1) * 128]);
        wr1[p] = pack2(p1[(2 * p) * 128], p1[(2 * p + 1) * 128]);
    }
    #pragma unroll
    for (int p = NREG; p < 64; p++) {
        ws[(p - NREG) * 512 + c0] = pack2(p0[(2 * p) * 128], p0[(2 * p + 1) * 128]);
        ws[(p - NREG) * 512 + c1] = pack2(p1[(2 * p) * 128], p1[(2 * p + 1) * 128]);
    }
    if (tid < 64) hs2[tid] = 0ull;   // h0 = 0
    __syncthreads();

    const float* preb = g_pre + (long long)b * TT * 512;
    const float* dtb  = dt    + (long long)b * TT;
    float*       seqb = g_seq + (long long)b * TT * 128;

    for (int t = 0; t < TT; t++) {
        // prefetch this step's pre values + dt (consumed after the MAC loop)
        const float pre0 = __ldg(preb + (long long)t * 512 + c0);
        const float pre1 = __ldg(preb + (long long)t * 512 + c1);
        const float dtt  = __ldg(dtb + t) * 10.0f;

        ull a0 = 0ull, a1 = 0ull;
        #pragma unroll
        for (int p = 0; p < NREG; p++) {
            ull hp = hs2[p];
            fma2(a0, wr0[p], hp);
            fma2(a1, wr1[p], hp);
        }
        #pragma unroll
        for (int p = NREG; p < 64; p++) {
            ull hp = hs2[p];
            fma2(a0, ws[(p - NREG) * 512 + c0], hp);
            fma2(a1, ws[(p - NREG) * 512 + c1], hp);
        }
        vsh[c0] = sum2(a0) + pre0;
        vsh[c1] = sum2(a1) + pre1;
        __syncthreads();   // all h reads done; v complete

        if (tid < 128) {
            const int j = tid;
            float ff1 = tanhf(vsh[j]);
            float ff2 = tanhf(vsh[128 + j]);
            float z   = vsh[256 + j] * dtt + vsh[384 + j];
            float gate = 1.0f / (1.0f + expf(-z));
            float hn = ff1 + gate * (ff2 - ff1);
            seqb[(long long)t * 128 + j] = hn;
            ((float*)hs2)[j] = hn;
        }
        __syncthreads();   // h ready for next step
    }
}

// =====================================================================
// K4: logits[tok] = seq[tok,:] . head_w + head_b   (one warp per token)
// =====================================================================
__global__ void __launch_bounds__(256) k4_head(
    const float* __restrict__ hw, const float* __restrict__ hb,
    float* __restrict__ out)
{
    const int tid = threadIdx.x;
    const int lane = tid & 31, w = tid >> 5;
    const long long tok = (long long)blockIdx.x * 8 + w;
    float4 s  = *(const float4*)(g_seq + tok * 128 + lane * 4);
    float4 hv = *(const float4*)(hw + lane * 4);
    float p = s.x * hv.x + s.y * hv.y + s.z * hv.z + s.w * hv.w;
    #pragma unroll
    for (int o = 16; o; o >>= 1) p += __shfl_xor_sync(0xffffffffu, p, o);
    if (lane == 0) out[tok] = p + hb[0];
}

// =====================================================================
extern "C" void kernel_launch(void* const* d_in, const int* in_sizes, int n_in,
                              void* d_out, int out_size)
{
    const float* x      = (const float*)d_in[0];
    const float* dt     = (const float*)d_in[1];
    const float* ln_in_g= (const float*)d_in[2];
    const float* ln_in_b= (const float*)d_in[3];
    const float* proj_w = (const float*)d_in[4];
    const float* proj_b = (const float*)d_in[5];
    const float* ln_p_g = (const float*)d_in[6];
    const float* ln_p_b = (const float*)d_in[7];
    const float* ff1_w  = (const float*)d_in[8];
    const float* ff1_b  = (const float*)d_in[9];
    const float* ff2_w  = (const float*)d_in[10];
    const float* ff2_b  = (const float*)d_in[11];
    const float* ta_w   = (const float*)d_in[12];
    const float* ta_b   = (const float*)d_in[13];
    const float* tb_w   = (const float*)d_in[14];
    const float* tb_b   = (const float*)d_in[15];
    const float* head_w = (const float*)d_in[16];
    const float* head_b = (const float*)d_in[17];
    float* out = (float*)d_out;

    cudaFuncSetAttribute(k2_pre, cudaFuncAttributeMaxDynamicSharedMemorySize, K2_SMEM_BYTES);
    cudaFuncSetAttribute(k3_rec, cudaFuncAttributeMaxDynamicSharedMemorySize, K3_SMEM_BYTES);

    k1_feat<<<NTOK / 8, 128>>>(x, ln_in_g, ln_in_b, proj_w, proj_b, ln_p_g, ln_p_b);

    dim3 g2(NTOK / 128, 4);
    k2_pre<<<g2, 256, K2_SMEM_BYTES>>>(ff1_w, ff2_w, ta_w, tb_w,
                                       ff1_b, ff2_b, ta_b, tb_b);

    k3_rec<<<BB, 256, K3_SMEM_BYTES>>>(ff1_w, ff2_w, ta_w, tb_w, dt);

    k4_head<<<NTOK / 8, 256>>>(head_w, head_b, out);
}

// round 14
// speedup vs baseline: 1.0004x; 1.0000x over previous
#include <cuda_runtime.h>
#include <cuda_bf16.h>

// Problem dims
#define BB 64
#define TT 4096
#define DD 67
#define HH 128
#define NTOK (BB * TT)   // 262144

typedef unsigned long long ull;

// Device scratch (allocation-free per harness rules)
__device__ float g_feat[(long long)NTOK * HH];    // 134 MB
__device__ float g_pre [(long long)NTOK * 512];   // 537 MB
__device__ float g_seq [(long long)NTOK * HH];    // 134 MB

// ---------------- f32x2 helpers ----------------
__device__ __forceinline__ void fma2(ull &acc, ull a, ull b) {
    asm("fma.rn.f32x2 %0, %1, %2, %0;" : "+l"(acc) : "l"(a), "l"(b));
}
__device__ __forceinline__ ull pack2(float lo, float hi) {
    ull u; asm("mov.b64 %0, {%1, %2};" : "=l"(u) : "f"(lo), "f"(hi)); return u;
}
__device__ __forceinline__ ull dup2(float a) {
    ull u; asm("mov.b64 %0, {%1, %1};" : "=l"(u) : "f"(a)); return u;
}
__device__ __forceinline__ float2 unpack2(ull u) {
    float2 r; asm("mov.b64 {%0, %1}, %2;" : "=f"(r.x), "=f"(r.y) : "l"(u)); return r;
}
__device__ __forceinline__ float sum2(ull u) {
    float2 r = unpack2(u); return r.x + r.y;
}

// =====================================================================
// K1: feat = silu(LN2(LN1(x) @ proj_w + proj_b))
//     128 threads, 8 tokens per block
// =====================================================================
__global__ void __launch_bounds__(128) k1_feat(
    const float* __restrict__ x,
    const float* __restrict__ g1, const float* __restrict__ b1,
    const float* __restrict__ pw, const float* __restrict__ pb,
    const float* __restrict__ g2, const float* __restrict__ b2)
{
    __shared__ __align__(16) float pwt[HH * 72];   // transposed weights [h][d]
    __shared__ __align__(16) float xs[8][72];
    __shared__ float ys[8][HH];
    __shared__ float mu[8], rs[8];

    const int tid = threadIdx.x;
    const long long n0 = (long long)blockIdx.x * 8;

    // load + transpose proj weights: pwt[h][d] = pw[d*128 + h]
    for (int i = tid; i < DD * HH; i += 128) {
        int d = i >> 7, h = i & 127;
        pwt[h * 72 + d] = pw[i];
    }
    // load x tile
    for (int i = tid; i < 8 * DD; i += 128) {
        int tk = i / DD, d = i % DD;
        xs[tk][d] = x[(n0 + tk) * DD + d];
    }
    __syncthreads();

    const int wid = tid >> 5, lane = tid & 31;
    // LN1 stats: warp w handles tokens 2w, 2w+1
    for (int tk = wid * 2; tk < wid * 2 + 2; tk++) {
        float s = 0.f, sq = 0.f;
        for (int d = lane; d < DD; d += 32) { float v = xs[tk][d]; s += v; sq += v * v; }
        #pragma unroll
        for (int o = 16; o; o >>= 1) {
            s  += __shfl_xor_sync(0xffffffffu, s,  o);
            sq += __shfl_xor_sync(0xffffffffu, sq, o);
        }
        if (lane == 0) {
            float m = s / (float)DD;
            mu[tk] = m;
            rs[tk] = rsqrtf(sq / (float)DD - m * m + 1e-5f);
        }
    }
    __syncthreads();
    for (int i = tid; i < 8 * DD; i += 128) {
        int tk = i / DD, d = i % DD;
        xs[tk][d] = (xs[tk][d] - mu[tk]) * rs[tk] * g1[d] + b1[d];
    }
    __syncthreads();

    // projection: thread h computes ys[tk][h] for all 8 tokens
    {
        const int h = tid;
        const float* wrow = pwt + h * 72;
        float acc[8];
        #pragma unroll
        for (int r = 0; r < 8; r++) acc[r] = pb[h];
        #pragma unroll
        for (int d4 = 0; d4 < 16; d4++) {
            float4 wv = *(const float4*)&wrow[d4 * 4];
            #pragma unroll
            for (int r = 0; r < 8; r++) {
                float4 xv = *(const float4*)&xs[r][d4 * 4];
                acc[r] += xv.x * wv.x + xv.y * wv.y + xv.z * wv.z + xv.w * wv.w;
            }
        }
        #pragma unroll
        for (int r = 0; r < 8; r++) {
            acc[r] += xs[r][64] * wrow[64] + xs[r][65] * wrow[65] + xs[r][66] * wrow[66];
            ys[r][h] = acc[r];
        }
    }
    __syncthreads();

    // LN2 stats over H=128
    for (int tk = wid * 2; tk < wid * 2 + 2; tk++) {
        float s = 0.f, sq = 0.f;
        #pragma unroll
        for (int hh = lane; hh < HH; hh += 32) { float v = ys[tk][hh]; s += v; sq += v * v; }
        #pragma unroll
        for (int o = 16; o; o >>= 1) {
            s  += __shfl_xor_sync(0xffffffffu, s,  o);
            sq += __shfl_xor_sync(0xffffffffu, sq, o);
        }
        if (lane == 0) {
            float m = s / (float)HH;
            mu[tk] = m;
            rs[tk] = rsqrtf(sq / (float)HH - m * m + 1e-5f);
        }
    }
    __syncthreads();
    {
        const int h = tid;
        const float gv = g2[h], bv = b2[h];
        #pragma unroll
        for (int r = 0; r < 8; r++) {
            float v = (ys[r][h] - mu[r]) * rs[r] * gv + bv;
            g_feat[(n0 + r) * HH + h] = v / (1.f + expf(-v));
        }
    }
}

// =====================================================================
// K2: pre[tok, g*128+n] = feat[tok,:] @ Wx_g + bias_g  (x-part rows 0..127)
//     tiles 128(M)x128(N), K=128; 256 threads, 8x8 micro-tiles, f32x2
// =====================================================================
#define K2_SMEM_BYTES ((128 * 129 + 128 * 132) * 4)

__global__ void __launch_bounds__(256) k2_pre(
    const float* __restrict__ w0, const float* __restrict__ w1,
    const float* __restrict__ w2, const float* __restrict__ w3,
    const float* __restrict__ bb0, const float* __restrict__ bb1,
    const float* __restrict__ bb2, const float* __restrict__ bb3)
{
    extern __shared__ float sm2[];
    float* As = sm2;                 // [128][129]
    float* Bs = sm2 + 128 * 129;     // [128][132]  (132*4 = 528 bytes, 16B multiple)

    const int g = blockIdx.y;
    const float* W  = (g == 0) ? w0  : (g == 1) ? w1  : (g == 2) ? w2  : w3;
    const float* Bv = (g == 0) ? bb0 : (g == 1) ? bb1 : (g == 2) ? bb2 : bb3;

    const int tid = threadIdx.x;
    const long long m0 = (long long)blockIdx.x * 128;

    for (int i = tid; i < 128 * 128; i += 256) {
        int m = i >> 7, k = i & 127;
        As[m * 129 + k] = g_feat[(m0 + m) * 128 + k];
    }
    for (int i = tid; i < 128 * 128; i += 256) {
        int k = i >> 7, n = i & 127;
        Bs[k * 132 + n] = W[k * 128 + n];   // x-part rows 0..127
    }
    __syncthreads();

    const int tx = tid & 15, ty = tid >> 4;
    ull acc[8][4];
    #pragma unroll
    for (int j = 0; j < 4; j++) {
        ull bb = pack2(Bv[tx * 8 + j * 2], Bv[tx * 8 + j * 2 + 1]);
        #pragma unroll
        for (int i = 0; i < 8; i++) acc[i][j] = bb;
    }

    const float* ap = &As[(ty * 8) * 129];
    for (int k = 0; k < 128; k++) {
        const ulonglong2* br = reinterpret_cast<const ulonglong2*>(Bs + k * 132 + tx * 8);
        ulonglong2 bA = br[0], bB = br[1];
        #pragma unroll
        for (int i = 0; i < 8; i++) {
            ull ad = dup2(ap[i * 129 + k]);
            fma2(acc[i][0], bA.x, ad);
            fma2(acc[i][1], bA.y, ad);
            fma2(acc[i][2], bB.x, ad);
            fma2(acc[i][3], bB.y, ad);
        }
    }

    #pragma unroll
    for (int i = 0; i < 8; i++) {
        long long row = m0 + ty * 8 + i;
        float* dst = g_pre + row * 512 + g * 128 + tx * 8;
        float2 p0 = unpack2(acc[i][0]), p1 = unpack2(acc[i][1]);
        float2 p2 = unpack2(acc[i][2]), p3 = unpack2(acc[i][3]);
        *(float4*)(dst)     = make_float4(p0.x, p0.y, p1.x, p1.y);
        *(float4*)(dst + 4) = make_float4(p2.x, p2.y, p3.x, p3.y);
    }
}

// =====================================================================
// K3: CfC recurrence. One CTA per batch, 256 threads, 2 columns/thread.
//     h-part weights: 48 k-pairs/col in registers + 16 k-pairs/col in smem.
// =====================================================================
#define NREG 48
#define NSM  (64 - NREG)   // 16 smem pairs per column
#define K3_SMEM_BYTES (512 + 2048 + NSM * 512 * 8)   // hs2 + v + ws = 68096

__global__ void __launch_bounds__(256, 1) k3_rec(
    const float* __restrict__ w0, const float* __restrict__ w1,
    const float* __restrict__ w2, const float* __restrict__ w3,
    const float* __restrict__ dt)
{
    extern __shared__ unsigned char sm3[];
    ull*   hs2 = (ull*)sm3;                          // 64 packed h pairs (512 B)
    float* vsh = (float*)(sm3 + 512);                // 512 floats (2 KB)
    ull*   ws  = (ull*)(sm3 + 512 + 2048);           // [NSM][512] weight pairs

    const int tid = threadIdx.x;
    const int b = blockIdx.x;
    const int c0 = tid, c1 = tid + 256;

    const float* gsel[4] = { w0, w1, w2, w3 };
    const int j0 = c0 & 127, j1 = c1 & 127;
    // base of h-part rows (row 128) at our column
    const float* p0 = gsel[c0 >> 7] + 128 * 128 + j0;
    const float* p1 = gsel[c1 >> 7] + 128 * 128 + j1;

    ull wr0[NREG], wr1[NREG];
    #pragma unroll
    for (int p = 0; p < NREG; p++) {
        wr0[p] = pack2(p0[(2 * p) * 128], p0[(2 * p + 1) * 128]);
        wr1[p] = pack2(p1[(2 * p) * 128], p1[(2 * p + 1) * 128]);
    }
    #pragma unroll
    for (int p = NREG; p < 64; p++) {
        ws[(p - NREG) * 512 + c0] = pack2(p0[(2 * p) * 128], p0[(2 * p + 1) * 128]);
        ws[(p - NREG) * 512 + c1] = pack2(p1[(2 * p) * 128], p1[(2 * p + 1) * 128]);
    }
    if (tid < 64) hs2[tid] = 0ull;   // h0 = 0
    __syncthreads();

    const float* preb = g_pre + (long long)b * TT * 512;
    const float* dtb  = dt    + (long long)b * TT;
    float*       seqb = g_seq + (long long)b * TT * 128;

    for (int t = 0; t < TT; t++) {
        // prefetch this step's pre values + dt (consumed after the MAC loop)
        const float pre0 = __ldg(preb + (long long)t * 512 + c0);
        const float pre1 = __ldg(preb + (long long)t * 512 + c1);
        const float dtt  = __ldg(dtb + t) * 10.0f;

        ull a0 = 0ull, a1 = 0ull;
        #pragma unroll
        for (int p = 0; p < NREG; p++) {
            ull hp = hs2[p];
            fma2(a0, wr0[p], hp);
            fma2(a1, wr1[p], hp);
        }
        #pragma unroll
        for (int p = NREG; p < 64; p++) {
            ull hp = hs2[p];
            fma2(a0, ws[(p - NREG) * 512 + c0], hp);
            fma2(a1, ws[(p - NREG) * 512 + c1], hp);
        }
        vsh[c0] = sum2(a0) + pre0;
        vsh[c1] = sum2(a1) + pre1;
        __syncthreads();   // all h reads done; v complete

        if (tid < 128) {
            const int j = tid;
            float ff1 = tanhf(vsh[j]);
            float ff2 = tanhf(vsh[128 + j]);
            float z   = vsh[256 + j] * dtt + vsh[384 + j];
            float gate = 1.0f / (1.0f + expf(-z));
            float hn = ff1 + gate * (ff2 - ff1);
            seqb[(long long)t * 128 + j] = hn;
            ((float*)hs2)[j] = hn;
        }
        __syncthreads();   // h ready for next step
    }
}

// =====================================================================
// K4: logits[tok] = seq[tok,:] . head_w + head_b   (one warp per token)
// =====================================================================
__global__ void __launch_bounds__(256) k4_head(
    const float* __restrict__ hw, const float* __restrict__ hb,
    float* __restrict__ out)
{
    const int tid = threadIdx.x;
    const int lane = tid & 31, w = tid >> 5;
    const long long tok = (long long)blockIdx.x * 8 + w;
    float4 s  = *(const float4*)(g_seq + tok * 128 + lane * 4);
    float4 hv = *(const float4*)(hw + lane * 4);
    float p = s.x * hv.x + s.y * hv.y + s.z * hv.z + s.w * hv.w;
    #pragma unroll
    for (int o = 16; o; o >>= 1) p += __shfl_xor_sync(0xffffffffu, p, o);
    if (lane == 0) out[tok] = p + hb[0];
}

// =====================================================================
extern "C" void kernel_launch(void* const* d_in, const int* in_sizes, int n_in,
                              void* d_out, int out_size)
{
    const float* x      = (const float*)d_in[0];
    const float* dt     = (const float*)d_in[1];
    const float* ln_in_g= (const float*)d_in[2];
    const float* ln_in_b= (const float*)d_in[3];
    const float* proj_w = (const float*)d_in[4];
    const float* proj_b = (const float*)d_in[5];
    const float* ln_p_g = (const float*)d_in[6];
    const float* ln_p_b = (const float*)d_in[7];
    const float* ff1_w  = (const float*)d_in[8];
    const float* ff1_b  = (const float*)d_in[9];
    const float* ff2_w  = (const float*)d_in[10];
    const float* ff2_b  = (const float*)d_in[11];
    const float* ta_w   = (const float*)d_in[12];
    const float* ta_b   = (const float*)d_in[13];
    const float* tb_w   = (const float*)d_in[14];
    const float* tb_b   = (const float*)d_in[15];
    const float* head_w = (const float*)d_in[16];
    const float* head_b = (const float*)d_in[17];
    float* out = (float*)d_out;

    cudaFuncSetAttribute(k2_pre, cudaFuncAttributeMaxDynamicSharedMemorySize, K2_SMEM_BYTES);
    cudaFuncSetAttribute(k3_rec, cudaFuncAttributeMaxDynamicSharedMemorySize, K3_SMEM_BYTES);

    k1_feat<<<NTOK / 8, 128>>>(x, ln_in_g, ln_in_b, proj_w, proj_b, ln_p_g, ln_p_b);

    dim3 g2(NTOK / 128, 4);
    k2_pre<<<g2, 256, K2_SMEM_BYTES>>>(ff1_w, ff2_w, ta_w, tb_w,
                                       ff1_b, ff2_b, ta_b, tb_b);

    k3_rec<<<BB, 256, K3_SMEM_BYTES>>>(ff1_w, ff2_w, ta_w, tb_w, dt);

    k4_head<<<NTOK / 8, 256>>>(head_w, head_b, out);
}

// round 15
// speedup vs baseline: 1.0007x; 1.0002x over previous
#include <cuda_runtime.h>
#include <cuda_bf16.h>

// Problem dims
#define BB 64
#define TT 4096
#define DD 67
#define HH 128
#define NTOK (BB * TT)   // 262144

typedef unsigned long long ull;

// Device scratch (allocation-free per harness rules)
__device__ float g_feat[(long long)NTOK * HH];    // 134 MB
__device__ float g_pre [(long long)NTOK * 512];   // 537 MB
__device__ float g_seq [(long long)NTOK * HH];    // 134 MB

// ---------------- f32x2 helpers ----------------
__device__ __forceinline__ void fma2(ull &acc, ull a, ull b) {
    asm("fma.rn.f32x2 %0, %1, %2, %0;" : "+l"(acc) : "l"(a), "l"(b));
}
__device__ __forceinline__ ull pack2(float lo, float hi) {
    ull u; asm("mov.b64 %0, {%1, %2};" : "=l"(u) : "f"(lo), "f"(hi)); return u;
}
__device__ __forceinline__ ull dup2(float a) {
    ull u; asm("mov.b64 %0, {%1, %1};" : "=l"(u) : "f"(a)); return u;
}
__device__ __forceinline__ float2 unpack2(ull u) {
    float2 r; asm("mov.b64 {%0, %1}, %2;" : "=f"(r.x), "=f"(r.y) : "l"(u)); return r;
}
__device__ __forceinline__ float sum2(ull u) {
    float2 r = unpack2(u); return r.x + r.y;
}

// =====================================================================
// K1: feat = silu(LN2(LN1(x) @ proj_w + proj_b))
//     128 threads, 8 tokens per block
// =====================================================================
__global__ void __launch_bounds__(128) k1_feat(
    const float* __restrict__ x,
    const float* __restrict__ g1, const float* __restrict__ b1,
    const float* __restrict__ pw, const float* __restrict__ pb,
    const float* __restrict__ g2, const float* __restrict__ b2)
{
    __shared__ __align__(16) float pwt[HH * 72];   // transposed weights [h][d]
    __shared__ __align__(16) float xs[8][72];
    __shared__ float ys[8][HH];
    __shared__ float mu[8], rs[8];

    const int tid = threadIdx.x;
    const long long n0 = (long long)blockIdx.x * 8;

    // load + transpose proj weights: pwt[h][d] = pw[d*128 + h]
    for (int i = tid; i < DD * HH; i += 128) {
        int d = i >> 7, h = i & 127;
        pwt[h * 72 + d] = pw[i];
    }
    // load x tile
    for (int i = tid; i < 8 * DD; i += 128) {
        int tk = i / DD, d = i % DD;
        xs[tk][d] = x[(n0 + tk) * DD + d];
    }
    __syncthreads();

    const int wid = tid >> 5, lane = tid & 31;
    // LN1 stats: warp w handles tokens 2w, 2w+1
    for (int tk = wid * 2; tk < wid * 2 + 2; tk++) {
        float s = 0.f, sq = 0.f;
        for (int d = lane; d < DD; d += 32) { float v = xs[tk][d]; s += v; sq += v * v; }
        #pragma unroll
        for (int o = 16; o; o >>= 1) {
            s  += __shfl_xor_sync(0xffffffffu, s,  o);
            sq += __shfl_xor_sync(0xffffffffu, sq, o);
        }
        if (lane == 0) {
            float m = s / (float)DD;
            mu[tk] = m;
            rs[tk] = rsqrtf(sq / (float)DD - m * m + 1e-5f);
        }
    }
    __syncthreads();
    for (int i = tid; i < 8 * DD; i += 128) {
        int tk = i / DD, d = i % DD;
        xs[tk][d] = (xs[tk][d] - mu[tk]) * rs[tk] * g1[d] + b1[d];
    }
    __syncthreads();

    // projection: thread h computes ys[tk][h] for all 8 tokens
    {
        const int h = tid;
        const float* wrow = pwt + h * 72;
        float acc[8];
        #pragma unroll
        for (int r = 0; r < 8; r++) acc[r] = pb[h];
        #pragma unroll
        for (int d4 = 0; d4 < 16; d4++) {
            float4 wv = *(const float4*)&wrow[d4 * 4];
            #pragma unroll
            for (int r = 0; r < 8; r++) {
                float4 xv = *(const float4*)&xs[r][d4 * 4];
                acc[r] += xv.x * wv.x + xv.y * wv.y + xv.z * wv.z + xv.w * wv.w;
            }
        }
        #pragma unroll
        for (int r = 0; r < 8; r++) {
            acc[r] += xs[r][64] * wrow[64] + xs[r][65] * wrow[65] + xs[r][66] * wrow[66];
            ys[r][h] = acc[r];
        }
    }
    __syncthreads();

    // LN2 stats over H=128
    for (int tk = wid * 2; tk < wid * 2 + 2; tk++) {
        float s = 0.f, sq = 0.f;
        #pragma unroll
        for (int hh = lane; hh < HH; hh += 32) { float v = ys[tk][hh]; s += v; sq += v * v; }
        #pragma unroll
        for (int o = 16; o; o >>= 1) {
            s  += __shfl_xor_sync(0xffffffffu, s,  o);
            sq += __shfl_xor_sync(0xffffffffu, sq, o);
        }
        if (lane == 0) {
            float m = s / (float)HH;
            mu[tk] = m;
            rs[tk] = rsqrtf(sq / (float)HH - m * m + 1e-5f);
        }
    }
    __syncthreads();
    {
        const int h = tid;
        const float gv = g2[h], bv = b2[h];
        #pragma unroll
        for (int r = 0; r < 8; r++) {
            float v = (ys[r][h] - mu[r]) * rs[r] * gv + bv;
            g_feat[(n0 + r) * HH + h] = v / (1.f + expf(-v));
        }
    }
}

// =====================================================================
// K2: pre[tok, g*128+n] = feat[tok,:] @ Wx_g + bias_g  (x-part rows 0..127)
//     tiles 128(M)x128(N), K=128; 256 threads, 8x8 micro-tiles, f32x2
// =====================================================================
#define K2_SMEM_BYTES ((128 * 129 + 128 * 132) * 4)

__global__ void __launch_bounds__(256) k2_pre(
    const float* __restrict__ w0, const float* __restrict__ w1,
    const float* __restrict__ w2, const float* __restrict__ w3,
    const float* __restrict__ bb0, const float* __restrict__ bb1,
    const float* __restrict__ bb2, const float* __restrict__ bb3)
{
    extern __shared__ float sm2[];
    float* As = sm2;                 // [128][129]
    float* Bs = sm2 + 128 * 129;     // [128][132]  (132*4 = 528 bytes, 16B multiple)

    const int g = blockIdx.y;
    const float* W  = (g == 0) ? w0  : (g == 1) ? w1  : (g == 2) ? w2  : w3;
    const float* Bv = (g == 0) ? bb0 : (g == 1) ? bb1 : (g == 2) ? bb2 : bb3;

    const int tid = threadIdx.x;
    const long long m0 = (long long)blockIdx.x * 128;

    for (int i = tid; i < 128 * 128; i += 256) {
        int m = i >> 7, k = i & 127;
        As[m * 129 + k] = g_feat[(m0 + m) * 128 + k];
    }
    for (int i = tid; i < 128 * 128; i += 256) {
        int k = i >> 7, n = i & 127;
        Bs[k * 132 + n] = W[k * 128 + n];   // x-part rows 0..127
    }
    __syncthreads();

    const int tx = tid & 15, ty = tid >> 4;
    ull acc[8][4];
    #pragma unroll
    for (int j = 0; j < 4; j++) {
        ull bb = pack2(Bv[tx * 8 + j * 2], Bv[tx * 8 + j * 2 + 1]);
        #pragma unroll
        for (int i = 0; i < 8; i++) acc[i][j] = bb;
    }

    const float* ap = &As[(ty * 8) * 129];
    for (int k = 0; k < 128; k++) {
        const ulonglong2* br = reinterpret_cast<const ulonglong2*>(Bs + k * 132 + tx * 8);
        ulonglong2 bA = br[0], bB = br[1];
        #pragma unroll
        for (int i = 0; i < 8; i++) {
            ull ad = dup2(ap[i * 129 + k]);
            fma2(acc[i][0], bA.x, ad);
            fma2(acc[i][1], bA.y, ad);
            fma2(acc[i][2], bB.x, ad);
            fma2(acc[i][3], bB.y, ad);
        }
    }

    #pragma unroll
    for (int i = 0; i < 8; i++) {
        long long row = m0 + ty * 8 + i;
        float* dst = g_pre + row * 512 + g * 128 + tx * 8;
        float2 p0 = unpack2(acc[i][0]), p1 = unpack2(acc[i][1]);
        float2 p2 = unpack2(acc[i][2]), p3 = unpack2(acc[i][3]);
        *(float4*)(dst)     = make_float4(p0.x, p0.y, p1.x, p1.y);
        *(float4*)(dst + 4) = make_float4(p2.x, p2.y, p3.x, p3.y);
    }
}

// =====================================================================
// K3: CfC recurrence. One CTA per batch, 256 threads, 2 columns/thread.
//     h-part weights: 48 k-pairs/col in registers + 16 k-pairs/col in smem.
// =====================================================================
#define NREG 48
#define NSM  (64 - NREG)   // 16 smem pairs per column
#define K3_SMEM_BYTES (512 + 2048 + NSM * 512 * 8)   // hs2 + v + ws = 68096

__global__ void __launch_bounds__(256, 1) k3_rec(
    const float* __restrict__ w0, const float* __restrict__ w1,
    const float* __restrict__ w2, const float* __restrict__ w3,
    const float* __restrict__ dt)
{
    extern __shared__ unsigned char sm3[];
    ull*   hs2 = (ull*)sm3;                          // 64 packed h pairs (512 B)
    float* vsh = (float*)(sm3 + 512);                // 512 floats (2 KB)
    ull*   ws  = (ull*)(sm3 + 512 + 2048);           // [NSM][512] weight pairs

    const int tid = threadIdx.x;
    const int b = blockIdx.x;
    const int c0 = tid, c1 = tid + 256;

    const float* gsel[4] = { w0, w1, w2, w3 };
    const int j0 = c0 & 127, j1 = c1 & 127;
    // base of h-part rows (row 128) at our column
    const float* p0 = gsel[c0 >> 7] + 128 * 128 + j0;
    const float* p1 = gsel[c1 >> 7] + 128 * 128 + j1;

    ull wr0[NREG], wr1[NREG];
    #pragma unroll
    for (int p = 0; p < NREG; p++) {
        wr0[p] = pack2(p0[(2 * p) * 128], p0[(2 * p + 1) * 128]);
        wr1[p] = pack2(p1[(2 * p) * 128], p1[(2 * p + 1) * 128]);
    }
    #pragma unroll
    for (int p = NREG; p < 64; p++) {
        ws[(p - NREG) * 512 + c0] = pack2(p0[(2 * p) * 128], p0[(2 * p + 1) * 128]);
        ws[(p - NREG) * 512 + c1] = pack2(p1[(2 * p) * 128], p1[(2 * p + 1) * 128]);
    }
    if (tid < 64) hs2[tid] = 0ull;   // h0 = 0
    __syncthreads();

    const float* preb = g_pre + (long long)b * TT * 512;
    const float* dtb  = dt    + (long long)b * TT;
    float*       seqb = g_seq + (long long)b * TT * 128;

    for (int t = 0; t < TT; t++) {
        // prefetch this step's pre values + dt (consumed after the MAC loop)
        const float pre0 = __ldg(preb + (long long)t * 512 + c0);
        const float pre1 = __ldg(preb + (long long)t * 512 + c1);
        const float dtt  = __ldg(dtb + t) * 10.0f;

        ull a0 = 0ull, a1 = 0ull;
        #pragma unroll
        for (int p = 0; p < NREG; p++) {
            ull hp = hs2[p];
            fma2(a0, wr0[p], hp);
            fma2(a1, wr1[p], hp);
        }
        #pragma unroll
        for (int p = NREG; p < 64; p++) {
            ull hp = hs2[p];
            fma2(a0, ws[(p - NREG) * 512 + c0], hp);
            fma2(a1, ws[(p - NREG) * 512 + c1], hp);
        }
        vsh[c0] = sum2(a0) + pre0;
        vsh[c1] = sum2(a1) + pre1;
        __syncthreads();   // all h reads done; v complete

        if (tid < 128) {
            const int j = tid;
            float ff1 = tanhf(vsh[j]);
            float ff2 = tanhf(vsh[128 + j]);
            float z   = vsh[256 + j] * dtt + vsh[384 + j];
            float gate = 1.0f / (1.0f + expf(-z));
            float hn = ff1 + gate * (ff2 - ff1);
            seqb[(long long)t * 128 + j] = hn;
            ((float*)hs2)[j] = hn;
        }
        __syncthreads();   // h ready for next step
    }
}

// =====================================================================
// K4: logits[tok] = seq[tok,:] . head_w + head_b   (one warp per token)
// =====================================================================
__global__ void __launch_bounds__(256) k4_head(
    const float* __restrict__ hw, const float* __restrict__ hb,
    float* __restrict__ out)
{
    const int tid = threadIdx.x;
    const int lane = tid & 31, w = tid >> 5;
    const long long tok = (long long)blockIdx.x * 8 + w;
    float4 s  = *(const float4*)(g_seq + tok * 128 + lane * 4);
    float4 hv = *(const float4*)(hw + lane * 4);
    float p = s.x * hv.x + s.y * hv.y + s.z * hv.z + s.w * hv.w;
    #pragma unroll
    for (int o = 16; o; o >>= 1) p += __shfl_xor_sync(0xffffffffu, p, o);
    if (lane == 0) out[tok] = p + hb[0];
}

// =====================================================================
extern "C" void kernel_launch(void* const* d_in, const int* in_sizes, int n_in,
                              void* d_out, int out_size)
{
    const float* x      = (const float*)d_in[0];
    const float* dt     = (const float*)d_in[1];
    const float* ln_in_g= (const float*)d_in[2];
    const float* ln_in_b= (const float*)d_in[3];
    const float* proj_w = (const float*)d_in[4];
    const float* proj_b = (const float*)d_in[5];
    const float* ln_p_g = (const float*)d_in[6];
    const float* ln_p_b = (const float*)d_in[7];
    const float* ff1_w  = (const float*)d_in[8];
    const float* ff1_b  = (const float*)d_in[9];
    const float* ff2_w  = (const float*)d_in[10];
    const float* ff2_b  = (const float*)d_in[11];
    const float* ta_w   = (const float*)d_in[12];
    const float* ta_b   = (const float*)d_in[13];
    const float* tb_w   = (const float*)d_in[14];
    const float* tb_b   = (const float*)d_in[15];
    const float* head_w = (const float*)d_in[16];
    const float* head_b = (const float*)d_in[17];
    float* out = (float*)d_out;

    cudaFuncSetAttribute(k2_pre, cudaFuncAttributeMaxDynamicSharedMemorySize, K2_SMEM_BYTES);
    cudaFuncSetAttribute(k3_rec, cudaFuncAttributeMaxDynamicSharedMemorySize, K3_SMEM_BYTES);

    k1_feat<<<NTOK / 8, 128>>>(x, ln_in_g, ln_in_b, proj_w, proj_b, ln_p_g, ln_p_b);

    dim3 g2(NTOK / 128, 4);
    k2_pre<<<g2, 256, K2_SMEM_BYTES>>>(ff1_w, ff2_w, ta_w, tb_w,
                                       ff1_b, ff2_b, ta_b, tb_b);

    k3_rec<<<BB, 256, K3_SMEM_BYTES>>>(ff1_w, ff2_w, ta_w, tb_w, dt);

    k4_head<<<NTOK / 8, 256>>>(head_w, head_b, out);
}

// round 16
// speedup vs baseline: 1.0214x; 1.0207x over previous
#include <cuda_runtime.h>
#include <cuda_bf16.h>

// Problem dims
#define BB 64
#define TT 4096
#define DD 67
#define HH 128
#define NTOK (BB * TT)   // 262144

typedef unsigned long long ull;

// Device scratch (allocation-free per harness rules)
__device__ float g_feat[(long long)NTOK * HH];    // 134 MB
__device__ float g_pre [(long long)NTOK * 512];   // 537 MB
__device__ float g_seq [(long long)NTOK * HH];    // 134 MB

// ---------------- f32x2 helpers ----------------
__device__ __forceinline__ void fma2(ull &acc, ull a, ull b) {
    asm("fma.rn.f32x2 %0, %1, %2, %0;" : "+l"(acc) : "l"(a), "l"(b));
}
__device__ __forceinline__ ull pack2(float lo, float hi) {
    ull u; asm("mov.b64 %0, {%1, %2};" : "=l"(u) : "f"(lo), "f"(hi)); return u;
}
__device__ __forceinline__ ull dup2(float a) {
    ull u; asm("mov.b64 %0, {%1, %1};" : "=l"(u) : "f"(a)); return u;
}
__device__ __forceinline__ float2 unpack2(ull u) {
    float2 r; asm("mov.b64 {%0, %1}, %2;" : "=f"(r.x), "=f"(r.y) : "l"(u)); return r;
}
__device__ __forceinline__ float sum2(ull u) {
    float2 r = unpack2(u); return r.x + r.y;
}

// fast, saturating tanh / sigmoid (MUFU-based; ~1e-6 rel err)
__device__ __forceinline__ float fast_tanh(float x) {
    float e = __expf(x + x);                  // exp(2x); inf OK
    return 1.0f - __fdividef(2.0f, e + 1.0f); // x->-inf: 1-2=-1; x->+inf: 1-0=1
}
__device__ __forceinline__ float fast_sig(float z) {
    return __fdividef(1.0f, 1.0f + __expf(-z));
}

// =====================================================================
// K1: feat = silu(LN2(LN1(x) @ proj_w + proj_b))
//     128 threads, 8 tokens per block
// =====================================================================
__global__ void __launch_bounds__(128) k1_feat(
    const float* __restrict__ x,
    const float* __restrict__ g1, const float* __restrict__ b1,
    const float* __restrict__ pw, const float* __restrict__ pb,
    const float* __restrict__ g2, const float* __restrict__ b2)
{
    __shared__ __align__(16) float pwt[HH * 72];   // transposed weights [h][d]
    __shared__ __align__(16) float xs[8][72];
    __shared__ float ys[8][HH];
    __shared__ float mu[8], rs[8];

    const int tid = threadIdx.x;
    const long long n0 = (long long)blockIdx.x * 8;

    for (int i = tid; i < DD * HH; i += 128) {
        int d = i >> 7, h = i & 127;
        pwt[h * 72 + d] = pw[i];
    }
    for (int i = tid; i < 8 * DD; i += 128) {
        int tk = i / DD, d = i % DD;
        xs[tk][d] = x[(n0 + tk) * DD + d];
    }
    __syncthreads();

    const int wid = tid >> 5, lane = tid & 31;
    for (int tk = wid * 2; tk < wid * 2 + 2; tk++) {
        float s = 0.f, sq = 0.f;
        for (int d = lane; d < DD; d += 32) { float v = xs[tk][d]; s += v; sq += v * v; }
        #pragma unroll
        for (int o = 16; o; o >>= 1) {
            s  += __shfl_xor_sync(0xffffffffu, s,  o);
            sq += __shfl_xor_sync(0xffffffffu, sq, o);
        }
        if (lane == 0) {
            float m = s / (float)DD;
            mu[tk] = m;
            rs[tk] = rsqrtf(sq / (float)DD - m * m + 1e-5f);
        }
    }
    __syncthreads();
    for (int i = tid; i < 8 * DD; i += 128) {
        int tk = i / DD, d = i % DD;
        xs[tk][d] = (xs[tk][d] - mu[tk]) * rs[tk] * g1[d] + b1[d];
    }
    __syncthreads();

    {
        const int h = tid;
        const float* wrow = pwt + h * 72;
        float acc[8];
        #pragma unroll
        for (int r = 0; r < 8; r++) acc[r] = pb[h];
        #pragma unroll
        for (int d4 = 0; d4 < 16; d4++) {
            float4 wv = *(const float4*)&wrow[d4 * 4];
            #pragma unroll
            for (int r = 0; r < 8; r++) {
                float4 xv = *(const float4*)&xs[r][d4 * 4];
                acc[r] += xv.x * wv.x + xv.y * wv.y + xv.z * wv.z + xv.w * wv.w;
            }
        }
        #pragma unroll
        for (int r = 0; r < 8; r++) {
            acc[r] += xs[r][64] * wrow[64] + xs[r][65] * wrow[65] + xs[r][66] * wrow[66];
            ys[r][h] = acc[r];
        }
    }
    __syncthreads();

    for (int tk = wid * 2; tk < wid * 2 + 2; tk++) {
        float s = 0.f, sq = 0.f;
        #pragma unroll
        for (int hh = lane; hh < HH; hh += 32) { float v = ys[tk][hh]; s += v; sq += v * v; }
        #pragma unroll
        for (int o = 16; o; o >>= 1) {
            s  += __shfl_xor_sync(0xffffffffu, s,  o);
            sq += __shfl_xor_sync(0xffffffffu, sq, o);
        }
        if (lane == 0) {
            float m = s / (float)HH;
            mu[tk] = m;
            rs[tk] = rsqrtf(sq / (float)HH - m * m + 1e-5f);
        }
    }
    __syncthreads();
    {
        const int h = tid;
        const float gv = g2[h], bv = b2[h];
        #pragma unroll
        for (int r = 0; r < 8; r++) {
            float v = (ys[r][h] - mu[r]) * rs[r] * gv + bv;
            g_feat[(n0 + r) * HH + h] = v / (1.f + expf(-v));
        }
    }
}

// =====================================================================
// K2: pre[tok, g*128+n] = feat[tok,:] @ Wx_g + bias_g  (x-part rows 0..127)
// =====================================================================
#define K2_SMEM_BYTES ((128 * 129 + 128 * 132) * 4)

__global__ void __launch_bounds__(256) k2_pre(
    const float* __restrict__ w0, const float* __restrict__ w1,
    const float* __restrict__ w2, const float* __restrict__ w3,
    const float* __restrict__ bb0, const float* __restrict__ bb1,
    const float* __restrict__ bb2, const float* __restrict__ bb3)
{
    extern __shared__ float sm2[];
    float* As = sm2;                 // [128][129]
    float* Bs = sm2 + 128 * 129;     // [128][132]

    const int g = blockIdx.y;
    const float* W  = (g == 0) ? w0  : (g == 1) ? w1  : (g == 2) ? w2  : w3;
    const float* Bv = (g == 0) ? bb0 : (g == 1) ? bb1 : (g == 2) ? bb2 : bb3;

    const int tid = threadIdx.x;
    const long long m0 = (long long)blockIdx.x * 128;

    for (int i = tid; i < 128 * 128; i += 256) {
        int m = i >> 7, k = i & 127;
        As[m * 129 + k] = g_feat[(m0 + m) * 128 + k];
    }
    for (int i = tid; i < 128 * 128; i += 256) {
        int k = i >> 7, n = i & 127;
        Bs[k * 132 + n] = W[k * 128 + n];
    }
    __syncthreads();

    const int tx = tid & 15, ty = tid >> 4;
    ull acc[8][4];
    #pragma unroll
    for (int j = 0; j < 4; j++) {
        ull bb = pack2(Bv[tx * 8 + j * 2], Bv[tx * 8 + j * 2 + 1]);
        #pragma unroll
        for (int i = 0; i < 8; i++) acc[i][j] = bb;
    }

    const float* ap = &As[(ty * 8) * 129];
    for (int k = 0; k < 128; k++) {
        const ulonglong2* br = reinterpret_cast<const ulonglong2*>(Bs + k * 132 + tx * 8);
        ulonglong2 bA = br[0], bB = br[1];
        #pragma unroll
        for (int i = 0; i < 8; i++) {
            ull ad = dup2(ap[i * 129 + k]);
            fma2(acc[i][0], bA.x, ad);
            fma2(acc[i][1], bA.y, ad);
            fma2(acc[i][2], bB.x, ad);
            fma2(acc[i][3], bB.y, ad);
        }
    }

    #pragma unroll
    for (int i = 0; i < 8; i++) {
        long long row = m0 + ty * 8 + i;
        float* dst = g_pre + row * 512 + g * 128 + tx * 8;
        float2 p0 = unpack2(acc[i][0]), p1 = unpack2(acc[i][1]);
        float2 p2 = unpack2(acc[i][2]), p3 = unpack2(acc[i][3]);
        *(float4*)(dst)     = make_float4(p0.x, p0.y, p1.x, p1.y);
        *(float4*)(dst + 4) = make_float4(p2.x, p2.y, p3.x, p3.y);
    }
}

// =====================================================================
// K3: CfC recurrence. One CTA per batch, 256 threads, 2 columns/thread.
//   Thread tid (j=tid&127, half=tid>>7):
//     half=0: columns j (ff1) and 128+j (ff2)  -> tanh both, combine
//     half=1: columns 256+j (ta) and 384+j (tb) -> sigmoid gate
//   Weights: 52 h-pairs/col in regs, 12 pairs/col in smem (ulonglong2-packed).
//   h broadcast via LDS.128 (packed pairs). pre/dt software-pipelined.
// =====================================================================
#define NREG 52
#define NREG2 (NREG / 2)          // 26 reg pair-pairs
#define NSM2 ((64 - NREG) / 2)    // 6 smem pair-pairs per column
// smem: hs2 (64 ull = 512 B) + gsh (128 f = 512 B) + ws (6*512*16 = 49152 B)
#define K3_SMEM_BYTES (512 + 512 + NSM2 * 512 * 16)

__global__ void __launch_bounds__(256, 1) k3_rec(
    const float* __restrict__ w0, const float* __restrict__ w1,
    const float* __restrict__ w2, const float* __restrict__ w3,
    const float* __restrict__ dt)
{
    extern __shared__ unsigned char sm3[];
    ull*        hs2  = (ull*)sm3;                       // 64 packed h pairs
    ulonglong2* hs2v = (ulonglong2*)sm3;                // 32 pair-pairs
    float*      hsf  = (float*)sm3;                     // scalar view
    float*      gsh  = (float*)(sm3 + 512);             // 128 gates
    ull*        ws   = (ull*)(sm3 + 1024);              // [NSM2][512][2]

    const int tid  = threadIdx.x;
    const int b    = blockIdx.x;
    const int j    = tid & 127;
    const int half = tid >> 7;
    const int c0 = half * 256 + j;        // ff1 / ta
    const int c1 = half * 256 + 128 + j;  // ff2 / tb

    const float* gsel[4] = { w0, w1, w2, w3 };
    const float* p0 = gsel[c0 >> 7] + 128 * 128 + (c0 & 127);
    const float* p1 = gsel[c1 >> 7] + 128 * 128 + (c1 & 127);

    ull wr0[NREG], wr1[NREG];
    #pragma unroll
    for (int p = 0; p < NREG; p++) {
        wr0[p] = pack2(p0[(2 * p) * 128], p0[(2 * p + 1) * 128]);
        wr1[p] = pack2(p1[(2 * p) * 128], p1[(2 * p + 1) * 128]);
    }
    // smem weights: pair-pairs q2 covers h-pairs NREG+2q2, NREG+2q2+1
    #pragma unroll
    for (int q2 = 0; q2 < NSM2; q2++) {
        int p = NREG + 2 * q2;
        ws[(q2 * 512 + c0) * 2 + 0] = pack2(p0[(2 * p)     * 128], p0[(2 * p + 1) * 128]);
        ws[(q2 * 512 + c0) * 2 + 1] = pack2(p0[(2 * p + 2) * 128], p0[(2 * p + 3) * 128]);
        ws[(q2 * 512 + c1) * 2 + 0] = pack2(p1[(2 * p)     * 128], p1[(2 * p + 1) * 128]);
        ws[(q2 * 512 + c1) * 2 + 1] = pack2(p1[(2 * p + 2) * 128], p1[(2 * p + 3) * 128]);
    }
    if (tid < 128) hsf[tid] = 0.f;   // h0 = 0
    __syncthreads();

    const float* preb = g_pre + (long long)b * TT * 512;
    const float* dtb  = dt    + (long long)b * TT;
    float*       seqb = g_seq + (long long)b * TT * 128 + j;

    const ulonglong2* wsv0 = (const ulonglong2*)(ws) + c0;   // stride 512 per q2
    const ulonglong2* wsv1 = (const ulonglong2*)(ws) + c1;

    // pipeline prologue: step-0 operands
    float pre0 = __ldg(preb + c0);
    float pre1 = __ldg(preb + c1);
    float dtt  = __ldg(dtb) * 10.0f;

    for (int t = 0; t < TT; t++) {
        // prefetch next step's operands (hidden under MAC loop)
        const float* pn  = preb + (t < TT - 1 ? 512 : 0);
        const float* dn  = dtb  + (t < TT - 1 ? t + 1 : t);
        float npre0 = __ldg(pn + c0);
        float npre1 = __ldg(pn + c1);
        float ndtt  = __ldg(dn) * 10.0f;

        ull a0 = 0ull, a1 = 0ull;
        #pragma unroll
        for (int p2 = 0; p2 < NREG2; p2++) {
            ulonglong2 hp = hs2v[p2];
            fma2(a0, wr0[2 * p2],     hp.x);
            fma2(a0, wr0[2 * p2 + 1], hp.y);
            fma2(a1, wr1[2 * p2],     hp.x);
            fma2(a1, wr1[2 * p2 + 1], hp.y);
        }
        #pragma unroll
        for (int q2 = 0; q2 < NSM2; q2++) {
            ulonglong2 hp = hs2v[NREG2 + q2];
            ulonglong2 wv0 = wsv0[q2 * 512];
            ulonglong2 wv1 = wsv1[q2 * 512];
            fma2(a0, wv0.x, hp.x);
            fma2(a0, wv0.y, hp.y);
            fma2(a1, wv1.x, hp.x);
            fma2(a1, wv1.y, hp.y);
        }

        float v0 = sum2(a0) + pre0;
        float v1 = sum2(a1) + pre1;

        float f1 = 0.f, f2 = 0.f;
        if (half == 0) {
            f1 = fast_tanh(v0);          // ff1
            f2 = fast_tanh(v1);          // ff2
        } else {
            float z = v0 * dtt + v1;     // ta*dt + tb
            gsh[j] = fast_sig(z);
        }
        __syncthreads();                 // gates visible; all h reads done

        if (half == 0) {
            float g  = gsh[j];
            float hn = f1 + g * (f2 - f1);
            hsf[j] = hn;
            seqb[(long long)t * 128] = hn;
        }
        __syncthreads();                 // h ready for next step

        preb += 512;
        pre0 = npre0; pre1 = npre1; dtt = ndtt;
    }
}

// =====================================================================
// K4: logits[tok] = seq[tok,:] . head_w + head_b   (one warp per token)
// =====================================================================
__global__ void __launch_bounds__(256) k4_head(
    const float* __restrict__ hw, const float* __restrict__ hb,
    float* __restrict__ out)
{
    const int tid = threadIdx.x;
    const int lane = tid & 31, w = tid >> 5;
    const long long tok = (long long)blockIdx.x * 8 + w;
    float4 s  = *(const float4*)(g_seq + tok * 128 + lane * 4);
    float4 hv = *(const float4*)(hw + lane * 4);
    float p = s.x * hv.x + s.y * hv.y + s.z * hv.z + s.w * hv.w;
    #pragma unroll
    for (int o = 16; o; o >>= 1) p += __shfl_xor_sync(0xffffffffu, p, o);
    if (lane == 0) out[tok] = p + hb[0];
}

// =====================================================================
extern "C" void kernel_launch(void* const* d_in, const int* in_sizes, int n_in,
                              void* d_out, int out_size)
{
    const float* x      = (const float*)d_in[0];
    const float* dt     = (const float*)d_in[1];
    const float* ln_in_g= (const float*)d_in[2];
    const float* ln_in_b= (const float*)d_in[3];
    const float* proj_w = (const float*)d_in[4];
    const float* proj_b = (const float*)d_in[5];
    const float* ln_p_g = (const float*)d_in[6];
    const float* ln_p_b = (const float*)d_in[7];
    const float* ff1_w  = (const float*)d_in[8];
    const float* ff1_b  = (const float*)d_in[9];
    const float* ff2_w  = (const float*)d_in[10];
    const float* ff2_b  = (const float*)d_in[11];
    const float* ta_w   = (const float*)d_in[12];
    const float* ta_b   = (const float*)d_in[13];
    const float* tb_w   = (const float*)d_in[14];
    const float* tb_b   = (const float*)d_in[15];
    const float* head_w = (const float*)d_in[16];
    const float* head_b = (const float*)d_in[17];
    float* out = (float*)d_out;

    cudaFuncSetAttribute(k2_pre, cudaFuncAttributeMaxDynamicSharedMemorySize, K2_SMEM_BYTES);
    cudaFuncSetAttribute(k3_rec, cudaFuncAttributeMaxDynamicSharedMemorySize, K3_SMEM_BYTES);

    k1_feat<<<NTOK / 8, 128>>>(x, ln_in_g, ln_in_b, proj_w, proj_b, ln_p_g, ln_p_b);

    dim3 g2(NTOK / 128, 4);
    k2_pre<<<g2, 256, K2_SMEM_BYTES>>>(ff1_w, ff2_w, ta_w, tb_w,
                                       ff1_b, ff2_b, ta_b, tb_b);

    k3_rec<<<BB, 256, K3_SMEM_BYTES>>>(ff1_w, ff2_w, ta_w, tb_w, dt);

    k4_head<<<NTOK / 8, 256>>>(head_w, head_b, out);
}